// round 1
// baseline (speedup 1.0000x reference)
#include <cuda_runtime.h>
#include <math.h>

// Problem constants (shapes fixed by the dataset)
#define S_LEN 1024
#define H_DIM 768
#define L_LAB 50
#define SW_WIN 10
#define D_DIM 2304            // 3*H
#define GK (L_LAB*H_DIM)      // 38400
#define SPLITS 16
#define KCHUNK (GK/SPLITS)    // 2400
#define NMAX 16384

// ---------------- scratch (device globals; no allocations allowed) ----------
__device__ float g_agg[S_LEN*L_LAB*H_DIM];   // (S, L, H) segment sums
__device__ float g_cnt[S_LEN*L_LAB];
__device__ float g_out1[S_LEN*H_DIM];        // GCN pre-activation (split-K accum)
__device__ float g_emb[S_LEN*H_DIM];         // x + relu(gcn)
__device__ float g_P[3*S_LEN*D_DIM];         // emb @ W1 blocks (start/end/attn)
__device__ float g_q[6*S_LEN];               // emb . ant_W chunks
__device__ float g_aw[NMAX*SW_WIN];          // softmax weights per span
__device__ float g_si[NMAX];
__device__ float g_sj[NMAX];
__device__ float g_ms[NMAX];                 // mention scores
__device__ int   g_idx[1024];                // topk indices (rank order)

// ---------------- edge scatter ---------------------------------------------
__global__ void scatter_kernel(const float* __restrict__ x,
                               const int* __restrict__ edges, int E) {
    int idx = blockIdx.x * blockDim.x + threadIdx.x;
    int total = E * H_DIM;
    if (idx >= total) return;
    int e = idx / H_DIM;
    int h = idx - e * H_DIM;
    int src = edges[3*e + 0];
    int tgt = edges[3*e + 1];
    int lbl = edges[3*e + 2];
    atomicAdd(&g_agg[(tgt * L_LAB + lbl) * H_DIM + h], x[src * H_DIM + h]);
}

__global__ void cnt_kernel(const int* __restrict__ edges, int E) {
    int e = blockIdx.x * blockDim.x + threadIdx.x;
    if (e >= E) return;
    atomicAdd(&g_cnt[edges[3*e + 1] * L_LAB + edges[3*e + 2]], 1.0f);
}

// ---------------- GEMM1: out1 = agg(1024 x 38400) @ gcn_W(38400 x 768) -----
// split-K over blockIdx.z, atomic accumulate into g_out1 (zeroed per launch).
__global__ __launch_bounds__(256, 2)
void gemm1_kernel(const float* __restrict__ W) {
    __shared__ float As[8][128];
    __shared__ float Bs[8][128];
    int tid = threadIdx.x;
    int bx = blockIdx.x, by = blockIdx.y, bz = blockIdx.z;
    int tx = tid & 15, ty = tid >> 4;
    int arow  = tid >> 1;
    int akoff = (tid & 1) * 4;
    int brow  = tid >> 5;
    int bcoff = (tid & 31) * 4;

    const float* A = g_agg + (by * 128) * GK;
    const float* B = W + bx * 128;

    float acc[8][8];
#pragma unroll
    for (int i = 0; i < 8; i++)
#pragma unroll
        for (int j = 0; j < 8; j++) acc[i][j] = 0.f;

    int k0 = bz * KCHUNK, kend = k0 + KCHUNK;
    for (; k0 < kend; k0 += 8) {
        float4 av = *(const float4*)(A + arow * GK + k0 + akoff);
        As[akoff + 0][arow] = av.x;
        As[akoff + 1][arow] = av.y;
        As[akoff + 2][arow] = av.z;
        As[akoff + 3][arow] = av.w;
        float4 bv = *(const float4*)(B + (k0 + brow) * H_DIM + bcoff);
        *(float4*)&Bs[brow][bcoff] = bv;
        __syncthreads();
#pragma unroll
        for (int kk = 0; kk < 8; kk++) {
            float a[8], b[8];
#pragma unroll
            for (int i = 0; i < 8; i++) a[i] = As[kk][ty * 8 + i];
#pragma unroll
            for (int j = 0; j < 8; j++) b[j] = Bs[kk][tx * 8 + j];
#pragma unroll
            for (int i = 0; i < 8; i++)
#pragma unroll
                for (int j = 0; j < 8; j++) acc[i][j] += a[i] * b[j];
        }
        __syncthreads();
    }
    int r0 = by * 128 + ty * 8;
    int c0 = bx * 128 + tx * 8;
#pragma unroll
    for (int i = 0; i < 8; i++)
#pragma unroll
        for (int j = 0; j < 8; j++)
            atomicAdd(&g_out1[(r0 + i) * H_DIM + c0 + j], acc[i][j]);
}

// ---------------- GCN epilogue: emb = x + relu((out1 + cnt@gcn_b)/deg) ------
__global__ void gcn_epi_kernel(const float* __restrict__ x,
                               const float* __restrict__ gcn_b) {
    int s = blockIdx.x, tid = threadIdx.x;
    __shared__ float c[L_LAB];
    if (tid < L_LAB) c[tid] = g_cnt[s * L_LAB + tid];
    __syncthreads();
    float deg = 0.f;
#pragma unroll
    for (int l = 0; l < L_LAB; l++) deg += c[l];
    deg = fmaxf(deg, 1.0f);
    float inv = 1.0f / deg;
    for (int d = tid; d < H_DIM; d += blockDim.x) {
        float bias = 0.f;
#pragma unroll
        for (int l = 0; l < L_LAB; l++) bias += c[l] * gcn_b[l * H_DIM + d];
        float v = (g_out1[s * H_DIM + d] + bias) * inv;
        g_emb[s * H_DIM + d] = x[s * H_DIM + d] + fmaxf(v, 0.f);
    }
}

// ---------------- GEMM_P: P[t] = emb(1024x768) @ W1[t*768:(t+1)*768, :] -----
__global__ __launch_bounds__(256, 2)
void gemmp_kernel(const float* __restrict__ W1) {
    __shared__ float As[8][128];
    __shared__ float Bs[8][128];
    int tid = threadIdx.x;
    int bx = blockIdx.x, by = blockIdx.y, t = blockIdx.z;
    int tx = tid & 15, ty = tid >> 4;
    int arow  = tid >> 1;
    int akoff = (tid & 1) * 4;
    int brow  = tid >> 5;
    int bcoff = (tid & 31) * 4;

    const float* A = g_emb + (by * 128) * H_DIM;
    const float* B = W1 + t * H_DIM * D_DIM + bx * 128;
    float* C = g_P + t * S_LEN * D_DIM;

    float acc[8][8];
#pragma unroll
    for (int i = 0; i < 8; i++)
#pragma unroll
        for (int j = 0; j < 8; j++) acc[i][j] = 0.f;

    for (int k0 = 0; k0 < H_DIM; k0 += 8) {
        float4 av = *(const float4*)(A + arow * H_DIM + k0 + akoff);
        As[akoff + 0][arow] = av.x;
        As[akoff + 1][arow] = av.y;
        As[akoff + 2][arow] = av.z;
        As[akoff + 3][arow] = av.w;
        float4 bv = *(const float4*)(B + (k0 + brow) * D_DIM + bcoff);
        *(float4*)&Bs[brow][bcoff] = bv;
        __syncthreads();
#pragma unroll
        for (int kk = 0; kk < 8; kk++) {
            float a[8], b[8];
#pragma unroll
            for (int i = 0; i < 8; i++) a[i] = As[kk][ty * 8 + i];
#pragma unroll
            for (int j = 0; j < 8; j++) b[j] = Bs[kk][tx * 8 + j];
#pragma unroll
            for (int i = 0; i < 8; i++)
#pragma unroll
                for (int j = 0; j < 8; j++) acc[i][j] += a[i] * b[j];
        }
        __syncthreads();
    }
    int r0 = by * 128 + ty * 8;
    int c0 = bx * 128 + tx * 8;
#pragma unroll
    for (int i = 0; i < 8; i++)
#pragma unroll
        for (int j = 0; j < 8; j++)
            C[(r0 + i) * D_DIM + c0 + j] = acc[i][j];
}

// ---------------- q tables: q[t][s] = emb[s] . ant_W[t*768 .. ] -------------
__global__ void qdot_kernel(const float* __restrict__ antW) {
    int wid = (blockIdx.x * blockDim.x + threadIdx.x) >> 5;
    int lane = threadIdx.x & 31;
    if (wid >= 6 * S_LEN) return;
    int t = wid >> 10;
    int s = wid & 1023;
    const float* v = antW + t * H_DIM;
    float p = 0.f;
    for (int h = lane; h < H_DIM; h += 32) p += g_emb[s * H_DIM + h] * v[h];
#pragma unroll
    for (int off = 16; off; off >>= 1) p += __shfl_xor_sync(0xffffffffu, p, off);
    if (lane == 0) g_q[t * S_LEN + s] = p;
}

// ---------------- span attention: softmax weights + s_i/s_j scalars ---------
__global__ void span_kernel(const int* __restrict__ ssp, const int* __restrict__ sep,
                            const float* __restrict__ attn_w,
                            const float* __restrict__ attn_b, int Nspan) {
    int wid = (blockIdx.x * blockDim.x + threadIdx.x) >> 5;
    int lane = threadIdx.x & 31;
    if (wid >= Nspan) return;
    int ss = ssp[wid], se = sep[wid];
    float sc[SW_WIN];
#pragma unroll
    for (int w = 0; w < SW_WIN; w++) {
        int pos = ss + w;
        int pc = min(pos, S_LEN - 1);
        float p = 0.f;
        for (int h = lane; h < H_DIM; h += 32) p += g_emb[pc * H_DIM + h] * attn_w[h];
#pragma unroll
        for (int off = 16; off; off >>= 1) p += __shfl_xor_sync(0xffffffffu, p, off);
        sc[w] = (pos <= se) ? (p + attn_b[0]) : -1e9f;
    }
    float mx = sc[0];
#pragma unroll
    for (int w = 1; w < SW_WIN; w++) mx = fmaxf(mx, sc[w]);
    float aw[SW_WIN];
    float Z = 0.f;
#pragma unroll
    for (int w = 0; w < SW_WIN; w++) { aw[w] = expf(sc[w] - mx); Z += aw[w]; }
    float inv = 1.0f / Z;
#pragma unroll
    for (int w = 0; w < SW_WIN; w++) aw[w] *= inv;
    if (lane == 0) {
        float si = g_q[0 * S_LEN + ss] + g_q[1 * S_LEN + se];
        float sj = g_q[3 * S_LEN + ss] + g_q[4 * S_LEN + se];
#pragma unroll
        for (int w = 0; w < SW_WIN; w++) {
            g_aw[wid * SW_WIN + w] = aw[w];
            int pc = min(ss + w, S_LEN - 1);
            si += aw[w] * g_q[2 * S_LEN + pc];
            sj += aw[w] * g_q[5 * S_LEN + pc];
        }
        g_si[wid] = si;
        g_sj[wid] = sj;
    }
}

// ---------------- mention scores via P-table combination --------------------
__global__ void mention_kernel(const int* __restrict__ ssp, const int* __restrict__ sep,
                               const float* __restrict__ b1,
                               const float* __restrict__ W2, int Nspan) {
    int n = blockIdx.x;
    int tid = threadIdx.x;
    __shared__ float aw[SW_WIN];
    __shared__ int pos[SW_WIN];
    __shared__ float red[256];
    int ss = ssp[n], se = sep[n];
    if (tid < SW_WIN) {
        aw[tid] = g_aw[n * SW_WIN + tid];
        pos[tid] = min(ss + tid, S_LEN - 1);
    }
    __syncthreads();
    const float* P1 = g_P + ss * D_DIM;
    const float* P2 = g_P + S_LEN * D_DIM + se * D_DIM;
    const float* P3 = g_P + 2 * S_LEN * D_DIM;
    float part = 0.f;
    for (int j = tid; j < D_DIM; j += 256) {
        float v = P1[j] + P2[j] + b1[j];
#pragma unroll
        for (int w = 0; w < SW_WIN; w++) v += aw[w] * P3[pos[w] * D_DIM + j];
        part += fmaxf(v, 0.f) * W2[j];
    }
    red[tid] = part;
    __syncthreads();
    for (int st = 128; st; st >>= 1) {
        if (tid < st) red[tid] += red[tid + st];
        __syncthreads();
    }
    if (tid == 0) g_ms[n] = red[0];
}

// ---------------- top-k: bitonic sort of packed (score desc, idx asc) keys --
__global__ void sort_kernel(int Nspan, int Ktop) {
    extern __shared__ unsigned long long keys[];
    const int n = NMAX;
    int tid = threadIdx.x;
    for (int i = tid; i < n; i += 1024) {
        unsigned long long kv;
        if (i < Nspan) {
            unsigned u = __float_as_uint(g_ms[i]);
            unsigned m = (u & 0x80000000u) ? ~u : (u | 0x80000000u);  // ascending map
            kv = (((unsigned long long)(~m)) << 32) | (unsigned)i;    // desc score, asc idx
        } else {
            kv = ~0ull;
        }
        keys[i] = kv;
    }
    __syncthreads();
    for (int k = 2; k <= n; k <<= 1) {
        for (int j = k >> 1; j; j >>= 1) {
            for (int i = tid; i < n; i += 1024) {
                int ixj = i ^ j;
                if (ixj > i) {
                    unsigned long long a = keys[i], b = keys[ixj];
                    bool up = ((i & k) == 0);
                    if ((a > b) == up) { keys[i] = b; keys[ixj] = a; }
                }
            }
            __syncthreads();
        }
    }
    for (int i = tid; i < Ktop; i += 1024) g_idx[i] = (int)(keys[i] & 0xFFFFFFFFu);
}

// ---------------- final antecedent matrix -----------------------------------
__global__ void final_kernel(const float* __restrict__ ant_b, float* __restrict__ out,
                             int Ktop, int total) {
    int p = blockIdx.x * blockDim.x + threadIdx.x;
    if (p >= total) return;
    int cols = Ktop + 1;
    int i = p / cols;
    int c = p - i * cols;
    float v;
    if (c == 0) {
        v = 0.0f;               // dummy column
    } else {
        int j = c - 1;
        v = (j >= i) ? -10000.0f : (g_si[g_idx[i]] + g_sj[g_idx[j]] + ant_b[0]);
    }
    out[p] = v;
}

// ---------------- launch -----------------------------------------------------
extern "C" void kernel_launch(void* const* d_in, const int* in_sizes, int n_in,
                              void* d_out, int out_size) {
    const float* x      = (const float*)d_in[0];
    const int*   edges  = (const int*)  d_in[1];
    const float* gcn_W  = (const float*)d_in[2];
    const float* gcn_b  = (const float*)d_in[3];
    const float* attn_w = (const float*)d_in[4];
    const float* attn_b = (const float*)d_in[5];
    const float* ms_W1  = (const float*)d_in[6];
    const float* ms_b1  = (const float*)d_in[7];
    const float* ms_W2  = (const float*)d_in[8];
    const float* ant_W  = (const float*)d_in[10];
    const float* ant_b  = (const float*)d_in[11];
    const int*   ssp    = (const int*)  d_in[12];
    const int*   sep    = (const int*)  d_in[13];

    int E = in_sizes[1] / 3;
    int Nspan = in_sizes[12];
    // out is (k, k+1): recover k from out_size
    int Ktop = (int)((sqrt(1.0 + 4.0 * (double)out_size) - 1.0) / 2.0 + 0.5);

    void *agg_p, *cnt_p, *out1_p;
    cudaGetSymbolAddress(&agg_p, g_agg);
    cudaGetSymbolAddress(&cnt_p, g_cnt);
    cudaGetSymbolAddress(&out1_p, g_out1);
    cudaMemsetAsync(agg_p, 0, sizeof(float) * S_LEN * L_LAB * H_DIM);
    cudaMemsetAsync(cnt_p, 0, sizeof(float) * S_LEN * L_LAB);
    cudaMemsetAsync(out1_p, 0, sizeof(float) * S_LEN * H_DIM);

    scatter_kernel<<<(E * H_DIM + 255) / 256, 256>>>(x, edges, E);
    cnt_kernel<<<(E + 255) / 256, 256>>>(edges, E);
    gemm1_kernel<<<dim3(H_DIM / 128, S_LEN / 128, SPLITS), 256>>>(gcn_W);
    gcn_epi_kernel<<<S_LEN, 256>>>(x, gcn_b);
    gemmp_kernel<<<dim3(D_DIM / 128, S_LEN / 128, 3), 256>>>(ms_W1);
    qdot_kernel<<<(6 * S_LEN) / 8, 256>>>(ant_W);
    span_kernel<<<(Nspan + 7) / 8, 256>>>(ssp, sep, attn_w, attn_b, Nspan);
    mention_kernel<<<Nspan, 256>>>(ssp, sep, ms_b1, ms_W2, Nspan);
    cudaFuncSetAttribute(sort_kernel, cudaFuncAttributeMaxDynamicSharedMemorySize, 131072);
    sort_kernel<<<1, 1024, 131072>>>(Nspan, Ktop);
    final_kernel<<<(out_size + 255) / 256, 256>>>(ant_b, (float*)d_out, Ktop, out_size);
}

// round 3
// speedup vs baseline: 1.9354x; 1.9354x over previous
#include <cuda_runtime.h>
#include <cuda_bf16.h>
#include <math.h>
#include <stdint.h>

// ---------------- problem constants ----------------
#define S_LEN 1024
#define H_DIM 768
#define L_LAB 50
#define SW_WIN 10
#define D_DIM 2304            // 3*H
#define GK (L_LAB*H_DIM)      // 38400
#define NMAX 16384
#define KSPLIT 8
#define KCHUNK (GK/KSPLIT)    // 4800
#define KT 64                 // K elements per smem tile
#define LDK 72                // padded smem row length (conflict-free frag loads)
#define KEEP 416              // per-block keep in stage-1 sort (>= topk)

// ---------------- scratch (device globals) ----------------
__device__ float g_agg[S_LEN*GK];            // (S, L*H) segment sums
__device__ float g_cnt[S_LEN*L_LAB];
__device__ float g_out1[S_LEN*H_DIM];        // GCN pre-activation (atomic accum)
__device__ float g_emb[S_LEN*H_DIM];
__device__ float g_P[3*S_LEN*D_DIM];
__device__ float g_q[7*S_LEN];               // 6 ant_W dots + attn score table
__device__ float g_aw[NMAX*SW_WIN];
__device__ float g_si[NMAX];
__device__ float g_sj[NMAX];
__device__ float g_ms[NMAX];
__device__ int   g_idx[1024];
__device__ unsigned long long g_skeys[16*KEEP];

__device__ __nv_bfloat16 g_Ahi[S_LEN*GK];    // agg split
__device__ __nv_bfloat16 g_Alo[S_LEN*GK];
__device__ __nv_bfloat16 g_Bhi[H_DIM*GK];    // gcn_W transposed split [768][38400]
__device__ __nv_bfloat16 g_Blo[H_DIM*GK];
__device__ __nv_bfloat16 g_W1thi[D_DIM*D_DIM]; // ms_W1 transposed split [2304][2304]
__device__ __nv_bfloat16 g_W1tlo[D_DIM*D_DIM];
__device__ __nv_bfloat16 g_Ehi[S_LEN*H_DIM]; // emb split
__device__ __nv_bfloat16 g_Elo[S_LEN*H_DIM];

// ---------------- edge scatter ----------------
__global__ void scatter_kernel(const float* __restrict__ x,
                               const int* __restrict__ edges, int E) {
    int idx = blockIdx.x * blockDim.x + threadIdx.x;
    int total = E * H_DIM;
    if (idx >= total) return;
    int e = idx / H_DIM;
    int h = idx - e * H_DIM;
    int src = edges[3*e + 0];
    int tgt = edges[3*e + 1];
    int lbl = edges[3*e + 2];
    atomicAdd(&g_agg[(tgt * L_LAB + lbl) * H_DIM + h], x[src * H_DIM + h]);
}

__global__ void cnt_kernel(const int* __restrict__ edges, int E) {
    int e = blockIdx.x * blockDim.x + threadIdx.x;
    if (e >= E) return;
    atomicAdd(&g_cnt[edges[3*e + 1] * L_LAB + edges[3*e + 2]], 1.0f);
}

// ---------------- fp32 -> bf16 hi/lo split (vectorized) ----------------
__global__ void cvt_split_kernel(const float* __restrict__ src,
                                 __nv_bfloat16* __restrict__ hi,
                                 __nv_bfloat16* __restrict__ lo, int n4) {
    int i = blockIdx.x * blockDim.x + threadIdx.x;
    if (i >= n4) return;
    float4 v = ((const float4*)src)[i];
    __nv_bfloat16 h0 = __float2bfloat16_rn(v.x);
    __nv_bfloat16 h1 = __float2bfloat16_rn(v.y);
    __nv_bfloat16 h2 = __float2bfloat16_rn(v.z);
    __nv_bfloat16 h3 = __float2bfloat16_rn(v.w);
    __nv_bfloat16 l0 = __float2bfloat16_rn(v.x - __bfloat162float(h0));
    __nv_bfloat16 l1 = __float2bfloat16_rn(v.y - __bfloat162float(h1));
    __nv_bfloat16 l2 = __float2bfloat16_rn(v.z - __bfloat162float(h2));
    __nv_bfloat16 l3 = __float2bfloat16_rn(v.w - __bfloat162float(h3));
    __nv_bfloat162* hp = (__nv_bfloat162*)hi;
    __nv_bfloat162* lp = (__nv_bfloat162*)lo;
    hp[2*i]   = __nv_bfloat162(h0, h1);
    hp[2*i+1] = __nv_bfloat162(h2, h3);
    lp[2*i]   = __nv_bfloat162(l0, l1);
    lp[2*i+1] = __nv_bfloat162(l2, l3);
}

// ---------------- transpose + split: src[R][C] -> dst[C][R] bf16 hi/lo ------
__global__ void transpose_split_kernel(const float* __restrict__ src,
                                       __nv_bfloat16* __restrict__ hi,
                                       __nv_bfloat16* __restrict__ lo,
                                       int R, int C) {
    __shared__ float t[32][33];
    int c0 = blockIdx.x * 32, r0 = blockIdx.y * 32;
    int tx = threadIdx.x, ty = threadIdx.y;
    t[ty][tx] = src[(size_t)(r0 + ty) * C + c0 + tx];
    __syncthreads();
    float v = t[tx][ty];
    __nv_bfloat16 h = __float2bfloat16_rn(v);
    __nv_bfloat16 l = __float2bfloat16_rn(v - __bfloat162float(h));
    size_t o = (size_t)(c0 + ty) * R + r0 + tx;
    hi[o] = h;
    lo[o] = l;
}

// ---------------- mma.sync bf16 split GEMM ----------------------------------
__device__ __forceinline__ void mma16816(float* c, const uint32_t* a, const uint32_t* b) {
    asm volatile("mma.sync.aligned.m16n8k16.row.col.f32.bf16.bf16.f32 "
        "{%0,%1,%2,%3}, {%4,%5,%6,%7}, {%8,%9}, {%0,%1,%2,%3};"
        : "+f"(c[0]), "+f"(c[1]), "+f"(c[2]), "+f"(c[3])
        : "r"(a[0]), "r"(a[1]), "r"(a[2]), "r"(a[3]), "r"(b[0]), "r"(b[1]));
}

// C[bm*128 + r][bn*128 + c] (+cOff) (+)= A(128 x K) * B(128 x K)^T over K chunk
__global__ __launch_bounds__(256, 2)
void mma_gemm_kernel(const __nv_bfloat16* __restrict__ Ahi, const __nv_bfloat16* __restrict__ Alo,
                     const __nv_bfloat16* __restrict__ Bhi, const __nv_bfloat16* __restrict__ Blo,
                     float* __restrict__ C, int ldA, int ldB, int ldC,
                     int ktiles, long long aOff, long long bOff, long long cOff, int atomic) {
    __shared__ __nv_bfloat16 sAh[128 * LDK];
    __shared__ __nv_bfloat16 sAl[128 * LDK];
    __shared__ __nv_bfloat16 sBh[128 * LDK];
    __shared__ __nv_bfloat16 sBl[128 * LDK];

    int tid = threadIdx.x;
    int wid = tid >> 5, lane = tid & 31;
    int wm = wid >> 2, wn = wid & 3;      // warp grid 2x4 -> warp tile 64x32
    int bn = blockIdx.x, bm = blockIdx.y, bz = blockIdx.z;

    const __nv_bfloat16* Ah = Ahi + (size_t)bm * 128 * ldA + (size_t)bz * aOff;
    const __nv_bfloat16* Al = Alo + (size_t)bm * 128 * ldA + (size_t)bz * aOff;
    const __nv_bfloat16* Bh = Bhi + (size_t)bn * 128 * ldB + (size_t)bz * bOff;
    const __nv_bfloat16* Bl = Blo + (size_t)bn * 128 * ldB + (size_t)bz * bOff;

    float acc[4][4][4];
#pragma unroll
    for (int i = 0; i < 4; i++)
#pragma unroll
        for (int j = 0; j < 4; j++)
#pragma unroll
            for (int r = 0; r < 4; r++) acc[i][j][r] = 0.f;

    int lrow = tid >> 3;          // 0..31 (row block of 4 rows handled per it)
    int lseg = tid & 7;           // 0..7 : 8-elem (16B) segment within 64-k row

    for (int t = 0; t < ktiles; t++) {
        int k0 = t * KT;
        // load 4 arrays: each thread 4 rows per array (128 rows / 32 row-threads)
#pragma unroll
        for (int rr = 0; rr < 4; rr++) {
            int row = lrow + rr * 32;
            uint4 vah = *(const uint4*)(Ah + (size_t)row * ldA + k0 + lseg * 8);
            uint4 val = *(const uint4*)(Al + (size_t)row * ldA + k0 + lseg * 8);
            uint4 vbh = *(const uint4*)(Bh + (size_t)row * ldB + k0 + lseg * 8);
            uint4 vbl = *(const uint4*)(Bl + (size_t)row * ldB + k0 + lseg * 8);
            *(uint4*)&sAh[row * LDK + lseg * 8] = vah;
            *(uint4*)&sAl[row * LDK + lseg * 8] = val;
            *(uint4*)&sBh[row * LDK + lseg * 8] = vbh;
            *(uint4*)&sBl[row * LDK + lseg * 8] = vbl;
        }
        __syncthreads();

#pragma unroll
        for (int ks = 0; ks < 4; ks++) {
            int kk = ks * 16 + (lane & 3) * 2;
            uint32_t ah[4][4], al[4][4], bh[4][2], bl[4][2];
#pragma unroll
            for (int mi = 0; mi < 4; mi++) {
                int row = wm * 64 + mi * 16 + (lane >> 2);
                ah[mi][0] = *(const uint32_t*)&sAh[row * LDK + kk];
                ah[mi][1] = *(const uint32_t*)&sAh[(row + 8) * LDK + kk];
                ah[mi][2] = *(const uint32_t*)&sAh[row * LDK + kk + 8];
                ah[mi][3] = *(const uint32_t*)&sAh[(row + 8) * LDK + kk + 8];
                al[mi][0] = *(const uint32_t*)&sAl[row * LDK + kk];
                al[mi][1] = *(const uint32_t*)&sAl[(row + 8) * LDK + kk];
                al[mi][2] = *(const uint32_t*)&sAl[row * LDK + kk + 8];
                al[mi][3] = *(const uint32_t*)&sAl[(row + 8) * LDK + kk + 8];
            }
#pragma unroll
            for (int ni = 0; ni < 4; ni++) {
                int nrow = wn * 32 + ni * 8 + (lane >> 2);
                bh[ni][0] = *(const uint32_t*)&sBh[nrow * LDK + kk];
                bh[ni][1] = *(const uint32_t*)&sBh[nrow * LDK + kk + 8];
                bl[ni][0] = *(const uint32_t*)&sBl[nrow * LDK + kk];
                bl[ni][1] = *(const uint32_t*)&sBl[nrow * LDK + kk + 8];
            }
#pragma unroll
            for (int mi = 0; mi < 4; mi++)
#pragma unroll
                for (int ni = 0; ni < 4; ni++) {
                    mma16816(acc[mi][ni], ah[mi], bh[ni]);
                    mma16816(acc[mi][ni], ah[mi], bl[ni]);
                    mma16816(acc[mi][ni], al[mi], bh[ni]);
                }
        }
        __syncthreads();
    }

    // epilogue
    float* Cb = C + cOff + (size_t)bm * 128 * ldC + (size_t)bn * 128;
#pragma unroll
    for (int mi = 0; mi < 4; mi++) {
#pragma unroll
        for (int ni = 0; ni < 4; ni++) {
            int r = wm * 64 + mi * 16 + (lane >> 2);
            int cc = wn * 32 + ni * 8 + (lane & 3) * 2;
            float* p0 = Cb + (size_t)r * ldC + cc;
            float* p1 = Cb + (size_t)(r + 8) * ldC + cc;
            if (atomic) {
                atomicAdd(p0,     acc[mi][ni][0]);
                atomicAdd(p0 + 1, acc[mi][ni][1]);
                atomicAdd(p1,     acc[mi][ni][2]);
                atomicAdd(p1 + 1, acc[mi][ni][3]);
            } else {
                *(float2*)p0 = make_float2(acc[mi][ni][0], acc[mi][ni][1]);
                *(float2*)p1 = make_float2(acc[mi][ni][2], acc[mi][ni][3]);
            }
        }
    }
}

// ---------------- GCN epilogue ----------------
__global__ void gcn_epi_kernel(const float* __restrict__ x,
                               const float* __restrict__ gcn_b) {
    int s = blockIdx.x, tid = threadIdx.x;
    __shared__ float c[L_LAB];
    if (tid < L_LAB) c[tid] = g_cnt[s * L_LAB + tid];
    __syncthreads();
    float deg = 0.f;
#pragma unroll
    for (int l = 0; l < L_LAB; l++) deg += c[l];
    deg = fmaxf(deg, 1.0f);
    float inv = 1.0f / deg;
    for (int d = tid; d < H_DIM; d += blockDim.x) {
        float bias = 0.f;
#pragma unroll
        for (int l = 0; l < L_LAB; l++) bias += c[l] * gcn_b[l * H_DIM + d];
        float v = (g_out1[s * H_DIM + d] + bias) * inv;
        g_emb[s * H_DIM + d] = x[s * H_DIM + d] + fmaxf(v, 0.f);
    }
}

// ---------------- q tables: 6 ant_W dots + attn score table -----------------
__global__ void qdot_kernel(const float* __restrict__ antW,
                            const float* __restrict__ attn_w) {
    int wid = (blockIdx.x * blockDim.x + threadIdx.x) >> 5;
    int lane = threadIdx.x & 31;
    if (wid >= 7 * S_LEN) return;
    int t = wid >> 10;
    int s = wid & 1023;
    const float* v = (t < 6) ? (antW + t * H_DIM) : attn_w;
    float p = 0.f;
    for (int h = lane; h < H_DIM; h += 32) p += g_emb[s * H_DIM + h] * v[h];
#pragma unroll
    for (int off = 16; off; off >>= 1) p += __shfl_xor_sync(0xffffffffu, p, off);
    if (lane == 0) g_q[t * S_LEN + s] = p;
}

// ---------------- span attention from score table ---------------------------
__global__ void span_kernel(const int* __restrict__ ssp, const int* __restrict__ sep,
                            const float* __restrict__ attn_b, int Nspan) {
    int n = blockIdx.x * blockDim.x + threadIdx.x;
    if (n >= Nspan) return;
    int ss = ssp[n], se = sep[n];
    float sc[SW_WIN];
#pragma unroll
    for (int w = 0; w < SW_WIN; w++) {
        int pos = ss + w;
        int pc = min(pos, S_LEN - 1);
        sc[w] = (pos <= se) ? (g_q[6 * S_LEN + pc] + attn_b[0]) : -1e9f;
    }
    float mx = sc[0];
#pragma unroll
    for (int w = 1; w < SW_WIN; w++) mx = fmaxf(mx, sc[w]);
    float aw[SW_WIN], Z = 0.f;
#pragma unroll
    for (int w = 0; w < SW_WIN; w++) { aw[w] = expf(sc[w] - mx); Z += aw[w]; }
    float inv = 1.0f / Z;
#pragma unroll
    for (int w = 0; w < SW_WIN; w++) aw[w] *= inv;
    float si = g_q[0 * S_LEN + ss] + g_q[1 * S_LEN + se];
    float sj = g_q[3 * S_LEN + ss] + g_q[4 * S_LEN + se];
#pragma unroll
    for (int w = 0; w < SW_WIN; w++) {
        g_aw[n * SW_WIN + w] = aw[w];
        int pc = min(ss + w, S_LEN - 1);
        si += aw[w] * g_q[2 * S_LEN + pc];
        sj += aw[w] * g_q[5 * S_LEN + pc];
    }
    g_si[n] = si;
    g_sj[n] = sj;
}

// ---------------- mention scores via P-table combination --------------------
__global__ void mention_kernel(const int* __restrict__ ssp, const int* __restrict__ sep,
                               const float* __restrict__ b1,
                               const float* __restrict__ W2,
                               const float* __restrict__ b2, int Nspan) {
    int n = blockIdx.x;
    int tid = threadIdx.x;
    __shared__ float aw[SW_WIN];
    __shared__ int pos[SW_WIN];
    __shared__ float red[256];
    int ss = ssp[n], se = sep[n];
    if (tid < SW_WIN) {
        aw[tid] = g_aw[n * SW_WIN + tid];
        pos[tid] = min(ss + tid, S_LEN - 1);
    }
    __syncthreads();
    const float* P1 = g_P + ss * D_DIM;
    const float* P2 = g_P + S_LEN * D_DIM + se * D_DIM;
    const float* P3 = g_P + 2 * S_LEN * D_DIM;
    float part = 0.f;
    for (int j = tid; j < D_DIM; j += 256) {
        float v = P1[j] + P2[j] + b1[j];
#pragma unroll
        for (int w = 0; w < SW_WIN; w++) v += aw[w] * P3[pos[w] * D_DIM + j];
        part += fmaxf(v, 0.f) * W2[j];
    }
    red[tid] = part;
    __syncthreads();
    for (int st = 128; st; st >>= 1) {
        if (tid < st) red[tid] += red[tid + st];
        __syncthreads();
    }
    if (tid == 0) g_ms[n] = red[0] + b2[0];
}

// ---------------- top-k: two-stage bitonic ----------------------------------
__device__ __forceinline__ unsigned long long enc_key(float f, int i) {
    unsigned u = __float_as_uint(f);
    unsigned m = (u & 0x80000000u) ? ~u : (u | 0x80000000u);     // monotone asc
    return (((unsigned long long)(~m)) << 32) | (unsigned)i;     // best first, tie->low idx
}

__global__ void sort1_kernel(int Nspan) {
    __shared__ unsigned long long k[1024];
    int b = blockIdx.x, tid = threadIdx.x;
    int i = b * 1024 + tid;
    k[tid] = (i < Nspan) ? enc_key(g_ms[i], i) : ~0ull;
    __syncthreads();
    for (int sz = 2; sz <= 1024; sz <<= 1) {
        for (int j = sz >> 1; j; j >>= 1) {
            int ixj = tid ^ j;
            if (ixj > tid) {
                bool up = ((tid & sz) == 0);
                unsigned long long a = k[tid], c = k[ixj];
                if ((a > c) == up) { k[tid] = c; k[ixj] = a; }
            }
            __syncthreads();
        }
    }
    if (tid < KEEP) g_skeys[b * KEEP + tid] = k[tid];
}

__global__ void sort2_kernel(int Ktop) {
    extern __shared__ unsigned long long k2[];
    const int n = 8192;
    int tid = threadIdx.x;
    for (int i = tid; i < n; i += 1024)
        k2[i] = (i < 16 * KEEP) ? g_skeys[i] : ~0ull;
    __syncthreads();
    for (int sz = 2; sz <= n; sz <<= 1) {
        for (int j = sz >> 1; j; j >>= 1) {
            for (int i = tid; i < n; i += 1024) {
                int ixj = i ^ j;
                if (ixj > i) {
                    bool up = ((i & sz) == 0);
                    unsigned long long a = k2[i], c = k2[ixj];
                    if ((a > c) == up) { k2[i] = c; k2[ixj] = a; }
                }
            }
            __syncthreads();
        }
    }
    for (int i = tid; i < Ktop; i += 1024) g_idx[i] = (int)(k2[i] & 0xFFFFFFFFu);
}

// ---------------- final antecedent matrix -----------------------------------
__global__ void final_kernel(const float* __restrict__ ant_b, float* __restrict__ out,
                             int Ktop, int total) {
    int p = blockIdx.x * blockDim.x + threadIdx.x;
    if (p >= total) return;
    int cols = Ktop + 1;
    int i = p / cols;
    int c = p - i * cols;
    float v;
    if (c == 0) v = 0.0f;
    else {
        int j = c - 1;
        v = (j >= i) ? -10000.0f : (g_si[g_idx[i]] + g_sj[g_idx[j]] + ant_b[0]);
    }
    out[p] = v;
}

// ---------------- launch -----------------------------------------------------
extern "C" void kernel_launch(void* const* d_in, const int* in_sizes, int n_in,
                              void* d_out, int out_size) {
    const float* x      = (const float*)d_in[0];
    const int*   edges  = (const int*)  d_in[1];
    const float* gcn_W  = (const float*)d_in[2];
    const float* gcn_b  = (const float*)d_in[3];
    const float* attn_w = (const float*)d_in[4];
    const float* attn_b = (const float*)d_in[5];
    const float* ms_W1  = (const float*)d_in[6];
    const float* ms_b1  = (const float*)d_in[7];
    const float* ms_W2  = (const float*)d_in[8];
    const float* ms_b2  = (const float*)d_in[9];
    const float* ant_W  = (const float*)d_in[10];
    const float* ant_b  = (const float*)d_in[11];
    const int*   ssp    = (const int*)  d_in[12];
    const int*   sep    = (const int*)  d_in[13];

    int E = in_sizes[1] / 3;
    int Nspan = in_sizes[12];
    int Ktop = (int)((sqrt(1.0 + 4.0 * (double)out_size) - 1.0) / 2.0 + 0.5);

    void *agg_p, *cnt_p, *out1_p;
    cudaGetSymbolAddress(&agg_p, g_agg);
    cudaGetSymbolAddress(&cnt_p, g_cnt);
    cudaGetSymbolAddress(&out1_p, g_out1);
    cudaMemsetAsync(agg_p, 0, sizeof(float) * S_LEN * GK);
    cudaMemsetAsync(cnt_p, 0, sizeof(float) * S_LEN * L_LAB);
    cudaMemsetAsync(out1_p, 0, sizeof(float) * S_LEN * H_DIM);

    void *ahi, *alo, *bhi, *blo, *w1h, *w1l, *ehi, *elo;
    cudaGetSymbolAddress(&ahi, g_Ahi);  cudaGetSymbolAddress(&alo, g_Alo);
    cudaGetSymbolAddress(&bhi, g_Bhi);  cudaGetSymbolAddress(&blo, g_Blo);
    cudaGetSymbolAddress(&w1h, g_W1thi); cudaGetSymbolAddress(&w1l, g_W1tlo);
    cudaGetSymbolAddress(&ehi, g_Ehi);  cudaGetSymbolAddress(&elo, g_Elo);
    void *aggf, *embf, *out1f, *pf;
    cudaGetSymbolAddress(&aggf, g_agg);
    cudaGetSymbolAddress(&embf, g_emb);
    cudaGetSymbolAddress(&out1f, g_out1);
    cudaGetSymbolAddress(&pf, g_P);

    cudaFuncSetAttribute(sort2_kernel, cudaFuncAttributeMaxDynamicSharedMemorySize, 65536);

    // graph edges + counts
    scatter_kernel<<<(E * H_DIM + 255) / 256, 256>>>(x, edges, E);
    cnt_kernel<<<(E + 255) / 256, 256>>>(edges, E);

    // weight preprocessing
    transpose_split_kernel<<<dim3(H_DIM / 32, GK / 32), dim3(32, 32)>>>(
        gcn_W, (__nv_bfloat16*)bhi, (__nv_bfloat16*)blo, GK, H_DIM);
    transpose_split_kernel<<<dim3(D_DIM / 32, D_DIM / 32), dim3(32, 32)>>>(
        ms_W1, (__nv_bfloat16*)w1h, (__nv_bfloat16*)w1l, D_DIM, D_DIM);

    // agg -> bf16 split
    cvt_split_kernel<<<(S_LEN * GK / 4 + 255) / 256, 256>>>(
        (const float*)aggf, (__nv_bfloat16*)ahi, (__nv_bfloat16*)alo, S_LEN * GK / 4);

    // GEMM1: out1 += agg @ gcn_W   (split-K=8, atomic)
    mma_gemm_kernel<<<dim3(H_DIM / 128, S_LEN / 128, KSPLIT), 256>>>(
        (const __nv_bfloat16*)ahi, (const __nv_bfloat16*)alo,
        (const __nv_bfloat16*)bhi, (const __nv_bfloat16*)blo,
        (float*)out1f, GK, GK, H_DIM,
        KCHUNK / KT, (long long)KCHUNK, (long long)KCHUNK, 0LL, 1);

    gcn_epi_kernel<<<S_LEN, 256>>>(x, gcn_b);

    // emb -> bf16 split
    cvt_split_kernel<<<(S_LEN * H_DIM / 4 + 255) / 256, 256>>>(
        (const float*)embf, (__nv_bfloat16*)ehi, (__nv_bfloat16*)elo, S_LEN * H_DIM / 4);

    // GEMM_P: P[t] = emb @ W1_block_t   (z = t selects weight block + C slab)
    mma_gemm_kernel<<<dim3(D_DIM / 128, S_LEN / 128, 3), 256>>>(
        (const __nv_bfloat16*)ehi, (const __nv_bfloat16*)elo,
        (const __nv_bfloat16*)w1h, (const __nv_bfloat16*)w1l,
        (float*)pf, H_DIM, D_DIM, D_DIM,
        H_DIM / KT, 0LL, (long long)H_DIM, (long long)S_LEN * D_DIM, 0);

    qdot_kernel<<<(7 * S_LEN * 32 + 255) / 256, 256>>>(ant_W, attn_w);
    span_kernel<<<(Nspan + 255) / 256, 256>>>(ssp, sep, attn_b, Nspan);
    mention_kernel<<<Nspan, 256>>>(ssp, sep, ms_b1, ms_W2, ms_b2, Nspan);
    sort1_kernel<<<16, 1024>>>(Nspan);
    sort2_kernel<<<1, 1024, 65536>>>(Ktop);
    final_kernel<<<(out_size + 255) / 256, 256>>>(ant_b, (float*)d_out, Ktop, out_size);
}

// round 4
// speedup vs baseline: 2.4813x; 1.2821x over previous
#include <cuda_runtime.h>
#include <cuda_bf16.h>
#include <math.h>
#include <stdint.h>

// ---------------- problem constants ----------------
#define S_LEN 1024
#define H_DIM 768
#define L_LAB 50
#define SW_WIN 10
#define D_DIM 2304            // 3*H
#define NMAX 16384
#define KT2 32                // K per pipeline stage
#define LDK2 40               // padded smem row (elems)
#define KEEP 416

// ---------------- scratch (device globals) ----------------
__device__ float g_T[L_LAB*S_LEN*H_DIM];     // per-label transformed x (157MB)
__device__ float g_cnt[S_LEN*L_LAB];
__device__ float g_out1[S_LEN*H_DIM];
__device__ float g_emb[S_LEN*H_DIM];
__device__ float g_P[3*S_LEN*D_DIM];
__device__ float g_q[7*S_LEN];
__device__ float g_aw[NMAX*SW_WIN];
__device__ float g_si[NMAX];
__device__ float g_sj[NMAX];
__device__ float g_ms[NMAX];
__device__ int   g_idx[1024];
__device__ unsigned long long g_skeys[16*KEEP];
__device__ int   g_estart[1025];
__device__ int   g_ecur[1024];
__device__ int   g_eord[1 << 17];

__device__ __nv_bfloat16 g_Xhi[S_LEN*H_DIM];
__device__ __nv_bfloat16 g_Xlo[S_LEN*H_DIM];
__device__ __nv_bfloat16 g_Bhi[L_LAB*H_DIM*H_DIM];   // W_l^T per label [l][d][h]
__device__ __nv_bfloat16 g_Blo[L_LAB*H_DIM*H_DIM];
__device__ __nv_bfloat16 g_W1thi[D_DIM*D_DIM];       // ms_W1^T [n][k]
__device__ __nv_bfloat16 g_W1tlo[D_DIM*D_DIM];
__device__ __nv_bfloat16 g_Ehi[S_LEN*H_DIM];
__device__ __nv_bfloat16 g_Elo[S_LEN*H_DIM];

// ---------------- cp.async helpers ----------------
#define CP_ASYNC16(saddr, gptr) \
    asm volatile("cp.async.cg.shared.global [%0], [%1], 16;" :: "r"(saddr), "l"(gptr) : "memory")
#define CP_COMMIT() asm volatile("cp.async.commit_group;" ::: "memory")
#define CP_WAIT1()  asm volatile("cp.async.wait_group 1;" ::: "memory")
#define CP_WAIT0()  asm volatile("cp.async.wait_group 0;" ::: "memory")

// ---------------- edge bucketing (counting sort by tgt) ----------------
__global__ void cnt_kernel(const int* __restrict__ edges, int E) {
    int e = blockIdx.x * blockDim.x + threadIdx.x;
    if (e >= E) return;
    atomicAdd(&g_cnt[edges[3*e + 1] * L_LAB + edges[3*e + 2]], 1.0f);
}

__global__ void hist_kernel(const int* __restrict__ edges, int E) {
    int e = blockIdx.x * blockDim.x + threadIdx.x;
    if (e >= E) return;
    atomicAdd(&g_ecur[edges[3*e + 1]], 1);
}

__global__ void scan_kernel() {
    __shared__ int sh[1024];
    int tid = threadIdx.x;
    int v = g_ecur[tid];
    sh[tid] = v;
    __syncthreads();
    for (int off = 1; off < 1024; off <<= 1) {
        int t = (tid >= off) ? sh[tid - off] : 0;
        __syncthreads();
        sh[tid] += t;
        __syncthreads();
    }
    g_estart[tid + 1] = sh[tid];
    if (tid == 0) g_estart[0] = 0;
    g_ecur[tid] = sh[tid] - v;    // exclusive prefix = bucket cursor
}

__global__ void place_kernel(const int* __restrict__ edges, int E) {
    int e = blockIdx.x * blockDim.x + threadIdx.x;
    if (e >= E) return;
    int pos = atomicAdd(&g_ecur[edges[3*e + 1]], 1);
    g_eord[pos] = e;
}

// ---------------- fp32 -> bf16 hi/lo split ----------------
__global__ void cvt_split_kernel(const float* __restrict__ src,
                                 __nv_bfloat16* __restrict__ hi,
                                 __nv_bfloat16* __restrict__ lo, int n4) {
    int i = blockIdx.x * blockDim.x + threadIdx.x;
    if (i >= n4) return;
    float4 v = ((const float4*)src)[i];
    __nv_bfloat16 h0 = __float2bfloat16_rn(v.x);
    __nv_bfloat16 h1 = __float2bfloat16_rn(v.y);
    __nv_bfloat16 h2 = __float2bfloat16_rn(v.z);
    __nv_bfloat16 h3 = __float2bfloat16_rn(v.w);
    __nv_bfloat16 l0 = __float2bfloat16_rn(v.x - __bfloat162float(h0));
    __nv_bfloat16 l1 = __float2bfloat16_rn(v.y - __bfloat162float(h1));
    __nv_bfloat16 l2 = __float2bfloat16_rn(v.z - __bfloat162float(h2));
    __nv_bfloat16 l3 = __float2bfloat16_rn(v.w - __bfloat162float(h3));
    __nv_bfloat162* hp = (__nv_bfloat162*)hi;
    __nv_bfloat162* lp = (__nv_bfloat162*)lo;
    hp[2*i]   = __nv_bfloat162(h0, h1);
    hp[2*i+1] = __nv_bfloat162(h2, h3);
    lp[2*i]   = __nv_bfloat162(l0, l1);
    lp[2*i+1] = __nv_bfloat162(l2, l3);
}

// ---- batched transpose+split: src[b][r][c] -> dst[b][c][r], bf16 hi/lo ----
__global__ void transpose_split_kernel(const float* __restrict__ src,
                                       __nv_bfloat16* __restrict__ hi,
                                       __nv_bfloat16* __restrict__ lo,
                                       int R, int C) {
    __shared__ float t[32][33];
    int b = blockIdx.z;
    int c0 = blockIdx.x * 32, r0 = blockIdx.y * 32;
    int tx = threadIdx.x, ty = threadIdx.y;
    size_t sbase = (size_t)b * R * C;
    t[ty][tx] = src[sbase + (size_t)(r0 + ty) * C + c0 + tx];
    __syncthreads();
    float v = t[tx][ty];
    __nv_bfloat16 h = __float2bfloat16_rn(v);
    __nv_bfloat16 l = __float2bfloat16_rn(v - __bfloat162float(h));
    size_t o = sbase + (size_t)(c0 + ty) * R + r0 + tx;
    hi[o] = h;
    lo[o] = l;
}

// ---------------- mma.sync bf16 split GEMM (cp.async double-buffered) -------
__device__ __forceinline__ void mma16816(float* c, const uint32_t* a, const uint32_t* b) {
    asm volatile("mma.sync.aligned.m16n8k16.row.col.f32.bf16.bf16.f32 "
        "{%0,%1,%2,%3}, {%4,%5,%6,%7}, {%8,%9}, {%0,%1,%2,%3};"
        : "+f"(c[0]), "+f"(c[1]), "+f"(c[2]), "+f"(c[3])
        : "r"(a[0]), "r"(a[1]), "r"(a[2]), "r"(a[3]), "r"(b[0]), "r"(b[1]));
}

// C[bz*cOff + (bm*128+r)*ldC + bn*128+c] (+)= A(128 x K) * B(128 x K)^T
__global__ __launch_bounds__(256, 2)
void mma_gemm_kernel(const __nv_bfloat16* __restrict__ Ahi, const __nv_bfloat16* __restrict__ Alo,
                     const __nv_bfloat16* __restrict__ Bhi, const __nv_bfloat16* __restrict__ Blo,
                     float* __restrict__ C, int ldA, int ldB, int ldC,
                     int ktiles, long long aOff, long long bOff, long long cOff, int atomic) {
    extern __shared__ __nv_bfloat16 sm[];   // 2 stages x 4 arrays x 128*LDK2
    uint32_t smb = (uint32_t)__cvta_generic_to_shared(sm);

    int tid = threadIdx.x;
    int wid = tid >> 5, lane = tid & 31;
    int wm = wid >> 2, wn = wid & 3;        // warp grid 2x4, warp tile 64x32
    int bn = blockIdx.x, bm = blockIdx.y, bz = blockIdx.z;

    const __nv_bfloat16* Ah = Ahi + (size_t)bm * 128 * ldA + (size_t)bz * aOff;
    const __nv_bfloat16* Al = Alo + (size_t)bm * 128 * ldA + (size_t)bz * aOff;
    const __nv_bfloat16* Bh = Bhi + (size_t)bn * 128 * ldB + (size_t)bz * bOff;
    const __nv_bfloat16* Bl = Blo + (size_t)bn * 128 * ldB + (size_t)bz * bOff;

    float acc[4][4][4];
#pragma unroll
    for (int i = 0; i < 4; i++)
#pragma unroll
        for (int j = 0; j < 4; j++)
#pragma unroll
            for (int r = 0; r < 4; r++) acc[i][j][r] = 0.f;

    const int STAGE = 4 * 128 * LDK2;       // elems per stage

    // issue one stage's loads: 2048 16B copies, 8 per thread
#define ISSUE(stg, t) do {                                                     \
        int k0 = (t) * KT2;                                                    \
        uint32_t sbase = smb + (stg) * STAGE * 2;                              \
        _Pragma("unroll")                                                      \
        for (int i = 0; i < 8; i++) {                                          \
            int o = tid + i * 256;                                             \
            int arr = o >> 9;                                                  \
            int rem = o & 511;                                                 \
            int row = rem >> 2;                                                \
            int quad = rem & 3;                                                \
            const __nv_bfloat16* src; int ld;                                  \
            if (arr == 0)      { src = Ah; ld = ldA; }                         \
            else if (arr == 1) { src = Al; ld = ldA; }                         \
            else if (arr == 2) { src = Bh; ld = ldB; }                         \
            else               { src = Bl; ld = ldB; }                         \
            const void* g = src + (size_t)row * ld + k0 + quad * 8;            \
            uint32_t sa = sbase + (uint32_t)(arr * 128 * LDK2 + row * LDK2 + quad * 8) * 2; \
            CP_ASYNC16(sa, g);                                                 \
        }                                                                      \
    } while (0)

    ISSUE(0, 0);
    CP_COMMIT();

    for (int t = 0; t < ktiles; t++) {
        int s = t & 1;
        if (t + 1 < ktiles) {
            ISSUE(s ^ 1, t + 1);
            CP_COMMIT();
            CP_WAIT1();
        } else {
            CP_WAIT0();
        }
        __syncthreads();

        const __nv_bfloat16* pAh = sm + s * STAGE;
        const __nv_bfloat16* pAl = pAh + 128 * LDK2;
        const __nv_bfloat16* pBh = pAh + 2 * 128 * LDK2;
        const __nv_bfloat16* pBl = pAh + 3 * 128 * LDK2;

#pragma unroll
        for (int ks = 0; ks < 2; ks++) {
            int kk = ks * 16 + (lane & 3) * 2;
            uint32_t ah[4][4], al[4][4], bh[4][2], bl[4][2];
#pragma unroll
            for (int mi = 0; mi < 4; mi++) {
                int row = wm * 64 + mi * 16 + (lane >> 2);
                ah[mi][0] = *(const uint32_t*)&pAh[row * LDK2 + kk];
                ah[mi][1] = *(const uint32_t*)&pAh[(row + 8) * LDK2 + kk];
                ah[mi][2] = *(const uint32_t*)&pAh[row * LDK2 + kk + 8];
                ah[mi][3] = *(const uint32_t*)&pAh[(row + 8) * LDK2 + kk + 8];
                al[mi][0] = *(const uint32_t*)&pAl[row * LDK2 + kk];
                al[mi][1] = *(const uint32_t*)&pAl[(row + 8) * LDK2 + kk];
                al[mi][2] = *(const uint32_t*)&pAl[row * LDK2 + kk + 8];
                al[mi][3] = *(const uint32_t*)&pAl[(row + 8) * LDK2 + kk + 8];
            }
#pragma unroll
            for (int ni = 0; ni < 4; ni++) {
                int nrow = wn * 32 + ni * 8 + (lane >> 2);
                bh[ni][0] = *(const uint32_t*)&pBh[nrow * LDK2 + kk];
                bh[ni][1] = *(const uint32_t*)&pBh[nrow * LDK2 + kk + 8];
                bl[ni][0] = *(const uint32_t*)&pBl[nrow * LDK2 + kk];
                bl[ni][1] = *(const uint32_t*)&pBl[nrow * LDK2 + kk + 8];
            }
#pragma unroll
            for (int mi = 0; mi < 4; mi++)
#pragma unroll
                for (int ni = 0; ni < 4; ni++) {
                    mma16816(acc[mi][ni], ah[mi], bh[ni]);
                    mma16816(acc[mi][ni], ah[mi], bl[ni]);
                    mma16816(acc[mi][ni], al[mi], bh[ni]);
                }
        }
        __syncthreads();
    }

    // epilogue (FIXED: cOff scaled by bz)
    float* Cb = C + (size_t)bz * cOff + (size_t)bm * 128 * ldC + (size_t)bn * 128;
#pragma unroll
    for (int mi = 0; mi < 4; mi++) {
#pragma unroll
        for (int ni = 0; ni < 4; ni++) {
            int r = wm * 64 + mi * 16 + (lane >> 2);
            int cc = wn * 32 + ni * 8 + (lane & 3) * 2;
            float* p0 = Cb + (size_t)r * ldC + cc;
            float* p1 = Cb + (size_t)(r + 8) * ldC + cc;
            if (atomic) {
                atomicAdd(p0,     acc[mi][ni][0]);
                atomicAdd(p0 + 1, acc[mi][ni][1]);
                atomicAdd(p1,     acc[mi][ni][2]);
                atomicAdd(p1 + 1, acc[mi][ni][3]);
            } else {
                *(float2*)p0 = make_float2(acc[mi][ni][0], acc[mi][ni][1]);
                *(float2*)p1 = make_float2(acc[mi][ni][2], acc[mi][ni][3]);
            }
        }
    }
#undef ISSUE
}

// ---------------- gather: out1[s] = sum_e T[lbl_e][src_e] -------------------
__global__ void gather_kernel(const int* __restrict__ edges) {
    int s = blockIdx.x;
    int tid = threadIdx.x;  // 192 (= 768/4)
    int beg = g_estart[s], end = g_estart[s + 1];
    float4 acc = make_float4(0.f, 0.f, 0.f, 0.f);
    int p = beg;
    for (; p + 1 < end; p += 2) {
        int e0 = g_eord[p], e1 = g_eord[p + 1];
        int s0 = edges[3*e0], l0 = edges[3*e0 + 2];
        int s1 = edges[3*e1], l1 = edges[3*e1 + 2];
        float4 v0 = ((const float4*)(g_T + ((size_t)l0 * S_LEN + s0) * H_DIM))[tid];
        float4 v1 = ((const float4*)(g_T + ((size_t)l1 * S_LEN + s1) * H_DIM))[tid];
        acc.x += v0.x + v1.x;
        acc.y += v0.y + v1.y;
        acc.z += v0.z + v1.z;
        acc.w += v0.w + v1.w;
    }
    if (p < end) {
        int e0 = g_eord[p];
        int s0 = edges[3*e0], l0 = edges[3*e0 + 2];
        float4 v0 = ((const float4*)(g_T + ((size_t)l0 * S_LEN + s0) * H_DIM))[tid];
        acc.x += v0.x; acc.y += v0.y; acc.z += v0.z; acc.w += v0.w;
    }
    ((float4*)(g_out1 + (size_t)s * H_DIM))[tid] = acc;
}

// ---------------- GCN epilogue ----------------
__global__ void gcn_epi_kernel(const float* __restrict__ x,
                               const float* __restrict__ gcn_b) {
    int s = blockIdx.x, tid = threadIdx.x;
    __shared__ float c[L_LAB];
    if (tid < L_LAB) c[tid] = g_cnt[s * L_LAB + tid];
    __syncthreads();
    float deg = 0.f;
#pragma unroll
    for (int l = 0; l < L_LAB; l++) deg += c[l];
    deg = fmaxf(deg, 1.0f);
    float inv = 1.0f / deg;
    for (int d = tid; d < H_DIM; d += blockDim.x) {
        float bias = 0.f;
#pragma unroll
        for (int l = 0; l < L_LAB; l++) bias += c[l] * gcn_b[l * H_DIM + d];
        float v = (g_out1[s * H_DIM + d] + bias) * inv;
        g_emb[s * H_DIM + d] = x[s * H_DIM + d] + fmaxf(v, 0.f);
    }
}

// ---------------- q tables: 6 ant_W dots + attn score table -----------------
__global__ void qdot_kernel(const float* __restrict__ antW,
                            const float* __restrict__ attn_w) {
    int wid = (blockIdx.x * blockDim.x + threadIdx.x) >> 5;
    int lane = threadIdx.x & 31;
    if (wid >= 7 * S_LEN) return;
    int t = wid >> 10;
    int s = wid & 1023;
    const float* v = (t < 6) ? (antW + t * H_DIM) : attn_w;
    float p = 0.f;
    for (int h = lane; h < H_DIM; h += 32) p += g_emb[s * H_DIM + h] * v[h];
#pragma unroll
    for (int off = 16; off; off >>= 1) p += __shfl_xor_sync(0xffffffffu, p, off);
    if (lane == 0) g_q[t * S_LEN + s] = p;
}

// ---------------- span attention from score table ---------------------------
__global__ void span_kernel(const int* __restrict__ ssp, const int* __restrict__ sep,
                            const float* __restrict__ attn_b, int Nspan) {
    int n = blockIdx.x * blockDim.x + threadIdx.x;
    if (n >= Nspan) return;
    int ss = ssp[n], se = sep[n];
    float sc[SW_WIN];
#pragma unroll
    for (int w = 0; w < SW_WIN; w++) {
        int pos = ss + w;
        int pc = min(pos, S_LEN - 1);
        sc[w] = (pos <= se) ? (g_q[6 * S_LEN + pc] + attn_b[0]) : -1e9f;
    }
    float mx = sc[0];
#pragma unroll
    for (int w = 1; w < SW_WIN; w++) mx = fmaxf(mx, sc[w]);
    float aw[SW_WIN], Z = 0.f;
#pragma unroll
    for (int w = 0; w < SW_WIN; w++) { aw[w] = expf(sc[w] - mx); Z += aw[w]; }
    float inv = 1.0f / Z;
#pragma unroll
    for (int w = 0; w < SW_WIN; w++) aw[w] *= inv;
    float si = g_q[0 * S_LEN + ss] + g_q[1 * S_LEN + se];
    float sj = g_q[3 * S_LEN + ss] + g_q[4 * S_LEN + se];
#pragma unroll
    for (int w = 0; w < SW_WIN; w++) {
        g_aw[n * SW_WIN + w] = aw[w];
        int pc = min(ss + w, S_LEN - 1);
        si += aw[w] * g_q[2 * S_LEN + pc];
        sj += aw[w] * g_q[5 * S_LEN + pc];
    }
    g_si[n] = si;
    g_sj[n] = sj;
}

// ---------------- mention scores, grouped by span start ---------------------
// block = start s (0..1022); spans with this start share P1[s] and P3 window.
__global__ void mention2_kernel(const float* __restrict__ b1,
                                const float* __restrict__ W2,
                                const float* __restrict__ b2) {
    int s = blockIdx.x;
    int tid = threadIdx.x;      // 256
    extern __shared__ float sh[];
    float* sP3 = sh;                    // [10][D_DIM]
    float* sP1 = sh + 10 * D_DIM;       // [D_DIM]
    __shared__ float red[8];

    const float4* P3base = (const float4*)(g_P + (size_t)2 * S_LEN * D_DIM);
#pragma unroll
    for (int w = 0; w < SW_WIN; w++) {
        int pc = min(s + w, S_LEN - 1);
        const float4* srcp = P3base + (size_t)pc * (D_DIM / 4);
        float4* dstp = (float4*)(sP3 + w * D_DIM);
        for (int j = tid; j < D_DIM / 4; j += 256) dstp[j] = srcp[j];
    }
    {
        const float4* srcp = (const float4*)(g_P + (size_t)s * D_DIM);
        float4* dstp = (float4*)sP1;
        for (int j = tid; j < D_DIM / 4; j += 256) dstp[j] = srcp[j];
    }
    __syncthreads();

    int nsp, base;
    if (s <= 1014) { nsp = 9; base = 9 * s; }
    else { int u = s - 1015; nsp = 1023 - s; base = 9135 + u * (17 - u) / 2; }

    for (int sp = 0; sp < nsp; sp++) {
        int n = base + sp;
        int e = s + 1 + sp;
        float aw[SW_WIN];
#pragma unroll
        for (int w = 0; w < SW_WIN; w++) aw[w] = g_aw[n * SW_WIN + w];
        const float* P2 = g_P + ((size_t)S_LEN + e) * D_DIM;
        float part = 0.f;
        for (int j = tid; j < D_DIM; j += 256) {
            float v = sP1[j] + P2[j] + b1[j];
#pragma unroll
            for (int w = 0; w < SW_WIN; w++) v += aw[w] * sP3[w * D_DIM + j];
            part += fmaxf(v, 0.f) * W2[j];
        }
#pragma unroll
        for (int off = 16; off; off >>= 1) part += __shfl_xor_sync(0xffffffffu, part, off);
        if ((tid & 31) == 0) red[tid >> 5] = part;
        __syncthreads();
        if (tid < 8) {
            float v2 = red[tid];
#pragma unroll
            for (int off = 4; off; off >>= 1) v2 += __shfl_xor_sync(0xffu, v2, off);
            if (tid == 0) g_ms[n] = v2 + b2[0];
        }
        __syncthreads();
    }
}

// ---------------- top-k: two-stage bitonic ----------------------------------
__device__ __forceinline__ unsigned long long enc_key(float f, int i) {
    unsigned u = __float_as_uint(f);
    unsigned m = (u & 0x80000000u) ? ~u : (u | 0x80000000u);
    return (((unsigned long long)(~m)) << 32) | (unsigned)i;
}

__global__ void sort1_kernel(int Nspan) {
    __shared__ unsigned long long k[1024];
    int b = blockIdx.x, tid = threadIdx.x;
    int i = b * 1024 + tid;
    k[tid] = (i < Nspan) ? enc_key(g_ms[i], i) : ~0ull;
    __syncthreads();
    for (int sz = 2; sz <= 1024; sz <<= 1) {
        for (int j = sz >> 1; j; j >>= 1) {
            int ixj = tid ^ j;
            if (ixj > tid) {
                bool up = ((tid & sz) == 0);
                unsigned long long a = k[tid], c = k[ixj];
                if ((a > c) == up) { k[tid] = c; k[ixj] = a; }
            }
            __syncthreads();
        }
    }
    if (tid < KEEP) g_skeys[b * KEEP + tid] = k[tid];
}

__global__ void sort2_kernel(int Ktop) {
    extern __shared__ unsigned long long k2[];
    const int n = 8192;
    int tid = threadIdx.x;
    for (int i = tid; i < n; i += 1024)
        k2[i] = (i < 16 * KEEP) ? g_skeys[i] : ~0ull;
    __syncthreads();
    for (int sz = 2; sz <= n; sz <<= 1) {
        for (int j = sz >> 1; j; j >>= 1) {
            for (int i = tid; i < n; i += 1024) {
                int ixj = i ^ j;
                if (ixj > i) {
                    bool up = ((i & sz) == 0);
                    unsigned long long a = k2[i], c = k2[ixj];
                    if ((a > c) == up) { k2[i] = c; k2[ixj] = a; }
                }
            }
            __syncthreads();
        }
    }
    for (int i = tid; i < Ktop; i += 1024) g_idx[i] = (int)(k2[i] & 0xFFFFFFFFu);
}

// ---------------- final antecedent matrix -----------------------------------
__global__ void final_kernel(const float* __restrict__ ant_b, float* __restrict__ out,
                             int Ktop, int total) {
    int p = blockIdx.x * blockDim.x + threadIdx.x;
    if (p >= total) return;
    int cols = Ktop + 1;
    int i = p / cols;
    int c = p - i * cols;
    float v;
    if (c == 0) v = 0.0f;
    else {
        int j = c - 1;
        v = (j >= i) ? -10000.0f : (g_si[g_idx[i]] + g_sj[g_idx[j]] + ant_b[0]);
    }
    out[p] = v;
}

// ---------------- launch -----------------------------------------------------
extern "C" void kernel_launch(void* const* d_in, const int* in_sizes, int n_in,
                              void* d_out, int out_size) {
    const float* x      = (const float*)d_in[0];
    const int*   edges  = (const int*)  d_in[1];
    const float* gcn_W  = (const float*)d_in[2];
    const float* gcn_b  = (const float*)d_in[3];
    const float* attn_w = (const float*)d_in[4];
    const float* attn_b = (const float*)d_in[5];
    const float* ms_W1  = (const float*)d_in[6];
    const float* ms_b1  = (const float*)d_in[7];
    const float* ms_W2  = (const float*)d_in[8];
    const float* ms_b2  = (const float*)d_in[9];
    const float* ant_W  = (const float*)d_in[10];
    const float* ant_b  = (const float*)d_in[11];
    const int*   ssp    = (const int*)  d_in[12];
    const int*   sep    = (const int*)  d_in[13];

    int E = in_sizes[1] / 3;
    int Nspan = in_sizes[12];
    int Ktop = (int)((sqrt(1.0 + 4.0 * (double)out_size) - 1.0) / 2.0 + 0.5);

    void *cnt_p, *ecur_p;
    cudaGetSymbolAddress(&cnt_p, g_cnt);
    cudaGetSymbolAddress(&ecur_p, g_ecur);
    cudaMemsetAsync(cnt_p, 0, sizeof(float) * S_LEN * L_LAB);
    cudaMemsetAsync(ecur_p, 0, sizeof(int) * 1024);

    void *xhi, *xlo, *bhi, *blo, *w1h, *w1l, *ehi, *elo, *tf, *embf, *pf;
    cudaGetSymbolAddress(&xhi, g_Xhi);  cudaGetSymbolAddress(&xlo, g_Xlo);
    cudaGetSymbolAddress(&bhi, g_Bhi);  cudaGetSymbolAddress(&blo, g_Blo);
    cudaGetSymbolAddress(&w1h, g_W1thi); cudaGetSymbolAddress(&w1l, g_W1tlo);
    cudaGetSymbolAddress(&ehi, g_Ehi);  cudaGetSymbolAddress(&elo, g_Elo);
    cudaGetSymbolAddress(&tf, g_T);
    cudaGetSymbolAddress(&embf, g_emb);
    cudaGetSymbolAddress(&pf, g_P);

    const int GEMM_SMEM = 2 * 4 * 128 * LDK2 * 2;   // 81920 bytes
    cudaFuncSetAttribute(mma_gemm_kernel, cudaFuncAttributeMaxDynamicSharedMemorySize, GEMM_SMEM);
    cudaFuncSetAttribute(sort2_kernel, cudaFuncAttributeMaxDynamicSharedMemorySize, 65536);
    const int MEN_SMEM = 11 * D_DIM * 4;            // 101376 bytes
    cudaFuncSetAttribute(mention2_kernel, cudaFuncAttributeMaxDynamicSharedMemorySize, MEN_SMEM);

    // edge bucketing + counts
    cnt_kernel<<<(E + 255) / 256, 256>>>(edges, E);
    hist_kernel<<<(E + 255) / 256, 256>>>(edges, E);
    scan_kernel<<<1, 1024>>>();
    place_kernel<<<(E + 255) / 256, 256>>>(edges, E);

    // weight preprocessing: per-label W_l^T, and ms_W1^T
    transpose_split_kernel<<<dim3(H_DIM / 32, H_DIM / 32, L_LAB), dim3(32, 32)>>>(
        gcn_W, (__nv_bfloat16*)bhi, (__nv_bfloat16*)blo, H_DIM, H_DIM);
    transpose_split_kernel<<<dim3(D_DIM / 32, D_DIM / 32, 1), dim3(32, 32)>>>(
        ms_W1, (__nv_bfloat16*)w1h, (__nv_bfloat16*)w1l, D_DIM, D_DIM);

    // x -> bf16 split
    cvt_split_kernel<<<(S_LEN * H_DIM / 4 + 255) / 256, 256>>>(
        x, (__nv_bfloat16*)xhi, (__nv_bfloat16*)xlo, S_LEN * H_DIM / 4);

    // GEMM_T: T[l] = x @ W_l^T   (z = label)
    mma_gemm_kernel<<<dim3(H_DIM / 128, S_LEN / 128, L_LAB), 256, GEMM_SMEM>>>(
        (const __nv_bfloat16*)xhi, (const __nv_bfloat16*)xlo,
        (const __nv_bfloat16*)bhi, (const __nv_bfloat16*)blo,
        (float*)tf, H_DIM, H_DIM, H_DIM,
        H_DIM / KT2, 0LL, (long long)H_DIM * H_DIM, (long long)S_LEN * H_DIM, 0);

    // gather per tgt
    gather_kernel<<<S_LEN, H_DIM / 4>>>(edges);

    gcn_epi_kernel<<<S_LEN, 256>>>(x, gcn_b);

    // emb -> bf16 split
    cvt_split_kernel<<<(S_LEN * H_DIM / 4 + 255) / 256, 256>>>(
        (const float*)embf, (__nv_bfloat16*)ehi, (__nv_bfloat16*)elo, S_LEN * H_DIM / 4);

    // GEMM_P: P[t] = emb @ W1_block_t   (z = t)
    mma_gemm_kernel<<<dim3(D_DIM / 128, S_LEN / 128, 3), 256, GEMM_SMEM>>>(
        (const __nv_bfloat16*)ehi, (const __nv_bfloat16*)elo,
        (const __nv_bfloat16*)w1h, (const __nv_bfloat16*)w1l,
        (float*)pf, H_DIM, D_DIM, D_DIM,
        H_DIM / KT2, 0LL, (long long)H_DIM, (long long)S_LEN * D_DIM, 0);

    qdot_kernel<<<(7 * S_LEN * 32 + 255) / 256, 256>>>(ant_W, attn_w);
    span_kernel<<<(Nspan + 255) / 256, 256>>>(ssp, sep, attn_b, Nspan);
    mention2_kernel<<<S_LEN - 1, 256, MEN_SMEM>>>(ms_b1, ms_W2, ms_b2);
    sort1_kernel<<<16, 1024>>>(Nspan);
    sort2_kernel<<<1, 1024, 65536>>>(Ktop);
    final_kernel<<<(out_size + 255) / 256, 256>>>(ant_b, (float*)d_out, Ktop, out_size);
}